// round 1
// baseline (speedup 1.0000x reference)
#include <cuda_runtime.h>
#include <cstdint>

// Fused submanifold sparse CNN:
//   mask = (x != 0); y0 = BN(x) masked; y1 = relu(subm_conv3x3(y0,w1)+b1) masked;
//   y2 = relu(subm_conv3x3(y1,w2)+b2) masked; out = NCHW(y2)
//
// One CTA per 8x32 output tile. Active-site compaction in SMEM; conv1 only at
// active halo sites; conv2 gathers over active neighbors (mask check) with
// 16 lanes x 4 out-channels per active site; dense coalesced writeout (zeros
// for inactive sites) from an SMEM staging buffer.

#define BATCH 4
#define HH 512
#define WW 512
#define TH 8
#define TW 32
#define RH 10          // y1 halo region rows  (TH+2)
#define RW 34          // y1 halo region cols  (TW+2)
#define RQ (RH*RW)     // 340
#define XH 12          // x region rows (TH+4)
#define XW 36          // x region cols (TW+4)
#define XN (XH*XW)     // 432
#define Y1S 341        // y1 row stride (odd -> conflict-free)
#define CAP 160        // active-output chunk capacity (mean ~26, Binom(256,0.1))
#define NT  256

__global__ __launch_bounds__(NT) void subm_net_kernel(
    const float* __restrict__ x,
    const float* __restrict__ bn_g, const float* __restrict__ bn_b,
    const float* __restrict__ bn_m, const float* __restrict__ bn_v,
    const float* __restrict__ w1,   const float* __restrict__ b1,
    const float* __restrict__ w2,   const float* __restrict__ b2,
    float* __restrict__ out)
{
    extern __shared__ float sm[];
    float* y1s = sm;                          // 32*341 floats
    float* y2s = y1s + 32 * Y1S;              // CAP*65 floats
    float* xs  = y2s + CAP * 65;              // 432 floats (BN'd, masked y0)
    int*   cnts  = (int*)(xs + XN);           // 2 ints
    short* hlist = (short*)(cnts + 2);        // 340
    short* clist = hlist + RQ;                // 256
    short* cidx  = clist + 256;               // 256
    unsigned char* m8 = (unsigned char*)(cidx + 256); // 432

    const int tid = threadIdx.x;
    const int b  = blockIdx.z;
    const int h0 = blockIdx.y * TH;
    const int w0 = blockIdx.x * TW;

    if (tid < 2) cnts[tid] = 0;

    const float scale = bn_g[0] * rsqrtf(bn_v[0] + 1e-5f);
    const float shift = bn_b[0] - bn_m[0] * scale;

    // ---- Phase 1: load x region (halo 2), BN + mask ----
    const float* xb = x + (size_t)b * HH * WW;
    for (int i = tid; i < XN; i += NT) {
        int rr = i / XW, cc = i - rr * XW;
        int gh = h0 - 2 + rr, gw = w0 - 2 + cc;
        float v = 0.f;
        if ((unsigned)gh < HH && (unsigned)gw < WW) v = xb[gh * WW + gw];
        bool act = (v != 0.f);
        xs[i] = act ? fmaf(v, scale, shift) : 0.f;
        m8[i] = act ? 1 : 0;
    }
    __syncthreads();

    // ---- Phase 2: build active-site lists (halo list + compacted core list) ----
    for (int q = tid; q < RQ; q += NT) {
        int hr = q / RW, hc = q - hr * RW;
        int xi = (hr + 1) * XW + (hc + 1);
        bool core = (hr >= 1 && hr <= TH && hc >= 1 && hc <= TW);
        if (m8[xi]) {
            int hi = atomicAdd(&cnts[0], 1);
            hlist[hi] = (short)q;
            if (core) {
                int ci = atomicAdd(&cnts[1], 1);
                int p = (hr - 1) * TW + (hc - 1);
                clist[ci] = (short)p;
                cidx[p] = (short)ci;
            }
        } else if (core) {
            cidx[(hr - 1) * TW + (hc - 1)] = -1;
        }
    }
    __syncthreads();

    const int nh = cnts[0];
    const int nc = cnts[1];

    // ---- Phase 3: conv1 (1->32) + ReLU at active halo sites only ----
    for (int it = tid; it < nh * 32; it += NT) {
        int ah = it >> 5, c1 = it & 31;
        int q  = hlist[ah];
        int hr = q / RW, hc = q - hr * RW;
        const float* xc = xs + hr * XW + hc;   // 3x3 window top-left in xs coords
        float acc = b1[c1];
        #pragma unroll
        for (int dr = 0; dr < 3; dr++)
            #pragma unroll
            for (int dc = 0; dc < 3; dc++)
                acc = fmaf(xc[dr * XW + dc], w1[(dr * 3 + dc) * 32 + c1], acc);
        y1s[c1 * Y1S + q] = fmaxf(acc, 0.f);
    }
    __syncthreads();

    // ---- Phase 4: conv2 (32->64) + ReLU at active core sites (gather) ----
    const int g    = tid & 15;   // 4 out-channels per lane-group
    const int slot = tid >> 4;   // 16 slots; 2 active sites per warp
    const float4 bias = ((const float4*)b2)[g];

    for (int base = 0; base < nc; base += CAP) {
        int cnt = min(nc - base, CAP);
        for (int s = slot; s < cnt; s += 16) {
            int p  = clist[base + s];
            int pr = p >> 5, pc = p & 31;
            float4 acc = bias;
            #pragma unroll
            for (int dr = 0; dr < 3; dr++) {
                #pragma unroll
                for (int dc = 0; dc < 3; dc++) {
                    int hr = pr + dr, hc = pc + dc;       // neighbor halo coords
                    if (m8[(hr + 1) * XW + (hc + 1)]) {
                        int q = hr * RW + hc;
                        const float4* wv = (const float4*)(w2 + (size_t)(dr * 3 + dc) * 2048) + g;
                        const float* yq = y1s + q;
                        #pragma unroll
                        for (int c1 = 0; c1 < 32; c1++) {
                            float  y  = yq[c1 * Y1S];      // lane-uniform broadcast
                            float4 wc = wv[c1 * 16];       // coalesced, L1-hot
                            acc.x = fmaf(y, wc.x, acc.x);
                            acc.y = fmaf(y, wc.y, acc.y);
                            acc.z = fmaf(y, wc.z, acc.z);
                            acc.w = fmaf(y, wc.w, acc.w);
                        }
                    }
                }
            }
            float* yo = y2s + s * 65 + g * 4;
            yo[0] = fmaxf(acc.x, 0.f);
            yo[1] = fmaxf(acc.y, 0.f);
            yo[2] = fmaxf(acc.z, 0.f);
            yo[3] = fmaxf(acc.w, 0.f);
        }
        __syncthreads();

        // ---- Phase 5: writeout ----
        float* ob = out + (size_t)b * 64 * HH * WW;
        if (base == 0) {
            // dense coalesced float4 stores; zeros for inactive (and idx>=CAP,
            // which are overwritten by later chunks -- never taken at 10% density)
            for (int it = tid; it < 64 * 64; it += NT) {
                int c2 = it >> 6, quad = it & 63;
                int p0 = quad * 4;
                int pr = p0 >> 5, pc = p0 & 31;
                float4 v;
                float* vv = (float*)&v;
                #pragma unroll
                for (int k = 0; k < 4; k++) {
                    int idx = cidx[p0 + k];
                    vv[k] = (idx >= 0 && idx < CAP) ? y2s[idx * 65 + c2] : 0.f;
                }
                *(float4*)(ob + ((size_t)c2 * HH + (h0 + pr)) * WW + (w0 + pc)) = v;
            }
        } else {
            // overflow chunk: scattered stores for the extra active sites
            for (int s2 = tid; s2 < cnt * 64; s2 += NT) {
                int s = s2 >> 6, c2 = s2 & 63;
                int p = clist[base + s];
                int pr = p >> 5, pc = p & 31;
                ob[((size_t)c2 * HH + (h0 + pr)) * WW + (w0 + pc)] = y2s[s * 65 + c2];
            }
        }
        __syncthreads();
    }
}

extern "C" void kernel_launch(void* const* d_in, const int* in_sizes, int n_in,
                              void* d_out, int out_size) {
    const float* x    = (const float*)d_in[0];
    const float* bn_g = (const float*)d_in[1];
    const float* bn_b = (const float*)d_in[2];
    const float* bn_m = (const float*)d_in[3];
    const float* bn_v = (const float*)d_in[4];
    const float* w1   = (const float*)d_in[5];
    const float* b1   = (const float*)d_in[6];
    const float* w2   = (const float*)d_in[7];
    const float* b2   = (const float*)d_in[8];
    float* out = (float*)d_out;

    // dynamic smem: floats + ints + shorts + chars
    int smem = (32 * Y1S + CAP * 65 + XN) * 4   // 86976
             + 2 * 4                            // counters
             + (RQ + 256 + 256) * 2             // short lists
             + XN;                              // mask bytes
    smem = (smem + 127) & ~127;

    static int attr_set = 0;
    cudaFuncSetAttribute(subm_net_kernel,
                         cudaFuncAttributeMaxDynamicSharedMemorySize, smem);
    (void)attr_set;

    dim3 grid(WW / TW, HH / TH, BATCH);
    subm_net_kernel<<<grid, NT, smem>>>(x, bn_g, bn_b, bn_m, bn_v,
                                        w1, b1, w2, b2, out);
}

// round 2
// speedup vs baseline: 1.2266x; 1.2266x over previous
#include <cuda_runtime.h>
#include <cstdint>

// Fused submanifold sparse CNN, direct-writeout version:
//   mask = (x != 0); y0 = BN(x) masked; y1 = relu(subm_conv3x3(y0,w1)+b1) masked;
//   y2 = relu(subm_conv3x3(y1,w2)+b2) masked; out = NCHW(y2)
//
// One CTA per 8x32 tile. Zero-fill output densely (STG.128), compute y1 only at
// active halo sites (compacted in SMEM), conv2 gathers active neighbors and
// writes results straight to global (scattered STG.32). No staging buffer.

#define BATCH 4
#define HH 512
#define WW 512
#define HWSZ (HH*WW)
#define TH 8
#define TW 32
#define RH 10          // halo rows (TH+2)
#define RW 34          // halo cols (TW+2)
#define RQ (RH*RW)     // 340
#define XH 12          // x region rows (TH+4)
#define XW 36          // x region cols (TW+4)
#define XN (XH*XW)     // 432
#define HCAP 224       // compacted halo-site capacity (mean ~34, Binom(340,0.1))
#define NT  256

__global__ __launch_bounds__(NT, 6) void subm_net_kernel(
    const float* __restrict__ x,
    const float* __restrict__ bn_g, const float* __restrict__ bn_b,
    const float* __restrict__ bn_m, const float* __restrict__ bn_v,
    const float* __restrict__ w1,   const float* __restrict__ b1,
    const float* __restrict__ w2,   const float* __restrict__ b2,
    float* __restrict__ out)
{
    extern __shared__ float sm[];
    float* y1c = sm;                          // HCAP*32 floats (compacted y1)
    float* xs  = y1c + HCAP * 32;             // XN floats (BN'd, masked y0)
    int*   cnts  = (int*)(xs + XN);           // 2 ints
    short* hlist = (short*)(cnts + 2);        // RQ  (halo q of each compact idx)
    short* hmap  = hlist + RQ;                // RQ  (q -> compact idx, -1 inactive)
    short* clist = hmap + RQ;                 // 256 (core p list)
    unsigned char* m8 = (unsigned char*)(clist + 256); // XN

    const int tid = threadIdx.x;
    const int b  = blockIdx.z;
    const int h0 = blockIdx.y * TH;
    const int w0 = blockIdx.x * TW;

    if (tid < 2) cnts[tid] = 0;

    const float scale = bn_g[0] * rsqrtf(bn_v[0] + 1e-5f);
    const float shift = bn_b[0] - bn_m[0] * scale;

    float* ob = out + (size_t)b * 64 * HWSZ;

    // ---- Phase 0: zero-fill the output tile (dense, coalesced, no LDS) ----
    {
        const float4 z4 = make_float4(0.f, 0.f, 0.f, 0.f);
        #pragma unroll
        for (int it = tid; it < 64 * TH * (TW / 4); it += NT) {   // 4096 float4
            int c2  = it >> 6;
            int rem = it & 63;
            int pr  = rem >> 3;
            int qd  = rem & 7;
            *(float4*)(ob + ((size_t)c2 * HH + (h0 + pr)) * WW + w0 + qd * 4) = z4;
        }
    }

    // ---- Phase 1: load x region (halo 2), BN + mask ----
    const float* xb = x + (size_t)b * HWSZ;
    for (int i = tid; i < XN; i += NT) {
        int rr = i / XW, cc = i - rr * XW;
        int gh = h0 - 2 + rr, gw = w0 - 2 + cc;
        float v = 0.f;
        if ((unsigned)gh < HH && (unsigned)gw < WW) v = xb[gh * WW + gw];
        bool act = (v != 0.f);
        xs[i] = act ? fmaf(v, scale, shift) : 0.f;
        m8[i] = act ? 1 : 0;
    }
    __syncthreads();

    // ---- Phase 2: build compacted halo list + core list ----
    for (int q = tid; q < RQ; q += NT) {
        int hr = q / RW, hc = q - hr * RW;
        int xi = (hr + 1) * XW + (hc + 1);
        bool core = (hr >= 1 && hr <= TH && hc >= 1 && hc <= TW);
        if (m8[xi]) {
            int hi = atomicAdd(&cnts[0], 1);
            if (hi < HCAP) {
                hlist[hi] = (short)q;
                hmap[q] = (short)hi;
            } else {
                hmap[q] = -1;   // statistically unreachable overflow guard
            }
            if (core) {
                int ci = atomicAdd(&cnts[1], 1);
                clist[ci] = (short)((hr - 1) * TW + (hc - 1));
            }
        } else {
            hmap[q] = -1;
        }
    }
    __syncthreads();

    const int nh = min(cnts[0], HCAP);
    const int nc = cnts[1];

    // ---- Phase 3: conv1 (1->32) + ReLU at active halo sites (compacted) ----
    for (int it = tid; it < nh * 32; it += NT) {
        int ah = it >> 5, c1 = it & 31;
        int q  = hlist[ah];
        int hr = q / RW, hc = q - hr * RW;
        const float* xc = xs + hr * XW + hc;   // 3x3 window top-left
        float acc = b1[c1];
        #pragma unroll
        for (int dr = 0; dr < 3; dr++)
            #pragma unroll
            for (int dc = 0; dc < 3; dc++)
                acc = fmaf(xc[dr * XW + dc], w1[(dr * 3 + dc) * 32 + c1], acc);
        y1c[ah * 32 + c1] = fmaxf(acc, 0.f);   // coalesced STS
    }
    __syncthreads();

    // ---- Phase 4: conv2 (32->64) + ReLU, direct scattered global write ----
    const int g    = tid & 15;   // lane-group: 4 consecutive out-channels
    const int slot = tid >> 4;   // 16 slots; 2 active sites per warp
    const float4 bias = ((const float4*)b2)[g];

    for (int s = slot; s < nc; s += 16) {
        int p  = clist[s];
        int pr = p >> 5, pc = p & 31;
        float4 acc = bias;
        #pragma unroll
        for (int dr = 0; dr < 3; dr++) {
            #pragma unroll
            for (int dc = 0; dc < 3; dc++) {
                int hidx = hmap[(pr + dr) * RW + (pc + dc)];
                if (hidx >= 0) {
                    const float4* yq = (const float4*)(y1c + hidx * 32);
                    const float4* wv = (const float4*)(w2 + (size_t)(dr * 3 + dc) * 2048) + g;
                    #pragma unroll
                    for (int c1q = 0; c1q < 8; c1q++) {
                        float4 y4 = yq[c1q];                 // LDS.128 broadcast
                        float4 wa = wv[(4 * c1q + 0) * 16];  // LDG.128, L1-hot
                        float4 wb = wv[(4 * c1q + 1) * 16];
                        float4 wc = wv[(4 * c1q + 2) * 16];
                        float4 wd = wv[(4 * c1q + 3) * 16];
                        acc.x = fmaf(y4.x, wa.x, acc.x);
                        acc.y = fmaf(y4.x, wa.y, acc.y);
                        acc.z = fmaf(y4.x, wa.z, acc.z);
                        acc.w = fmaf(y4.x, wa.w, acc.w);
                        acc.x = fmaf(y4.y, wb.x, acc.x);
                        acc.y = fmaf(y4.y, wb.y, acc.y);
                        acc.z = fmaf(y4.y, wb.z, acc.z);
                        acc.w = fmaf(y4.y, wb.w, acc.w);
                        acc.x = fmaf(y4.z, wc.x, acc.x);
                        acc.y = fmaf(y4.z, wc.y, acc.y);
                        acc.z = fmaf(y4.z, wc.z, acc.z);
                        acc.w = fmaf(y4.z, wc.w, acc.w);
                        acc.x = fmaf(y4.w, wd.x, acc.x);
                        acc.y = fmaf(y4.w, wd.y, acc.y);
                        acc.z = fmaf(y4.w, wd.z, acc.z);
                        acc.w = fmaf(y4.w, wd.w, acc.w);
                    }
                }
            }
        }
        float* op = ob + (size_t)(4 * g) * HWSZ + (size_t)(h0 + pr) * WW + (w0 + pc);
        op[0]            = fmaxf(acc.x, 0.f);
        op[(size_t)HWSZ]     = fmaxf(acc.y, 0.f);
        op[(size_t)2 * HWSZ] = fmaxf(acc.z, 0.f);
        op[(size_t)3 * HWSZ] = fmaxf(acc.w, 0.f);
    }
}

extern "C" void kernel_launch(void* const* d_in, const int* in_sizes, int n_in,
                              void* d_out, int out_size) {
    const float* x    = (const float*)d_in[0];
    const float* bn_g = (const float*)d_in[1];
    const float* bn_b = (const float*)d_in[2];
    const float* bn_m = (const float*)d_in[3];
    const float* bn_v = (const float*)d_in[4];
    const float* w1   = (const float*)d_in[5];
    const float* b1   = (const float*)d_in[6];
    const float* w2   = (const float*)d_in[7];
    const float* b2   = (const float*)d_in[8];
    float* out = (float*)d_out;

    int smem = (HCAP * 32 + XN) * 4      // y1c + xs
             + 2 * 4                      // counters
             + (RQ + RQ + 256) * 2        // hlist + hmap + clist
             + XN;                        // m8
    smem = (smem + 127) & ~127;

    cudaFuncSetAttribute(subm_net_kernel,
                         cudaFuncAttributeMaxDynamicSharedMemorySize, smem);

    dim3 grid(WW / TW, HH / TH, BATCH);
    subm_net_kernel<<<grid, NT, smem>>>(x, bn_g, bn_b, bn_m, bn_v,
                                        w1, b1, w2, b2, out);
}